// round 7
// baseline (speedup 1.0000x reference)
#include <cuda_runtime.h>
#include <math_constants.h>

#define BB 512
#define TT 1024
#define KK 48

typedef unsigned long long ull;

__device__ __forceinline__ ull pack2(float lo, float hi) {
    return ((ull)__float_as_uint(hi) << 32) | (ull)__float_as_uint(lo);
}
__device__ __forceinline__ float ulo(ull v){ return __uint_as_float((unsigned)v); }
__device__ __forceinline__ float uhi(ull v){ return __uint_as_float((unsigned)(v >> 32)); }

#define FFMA2(d,a,b,c) asm("fma.rn.f32x2 %0, %1, %2, %3;" : "=l"(d) : "l"(a), "l"(b), "l"(c))
#define FADD2(d,a,b)   asm("add.rn.f32x2 %0, %1, %2;"     : "=l"(d) : "l"(a), "l"(b))

// ---------------------------------------------------------------------------
// One block (32 threads, 1 warp) handles TWO batches (2*blockIdx, +1).
// Lane l owns states 2l, 2l+1 for both batches (lanes 24..31: zero rows).
// Linear-space recurrence per batch:
//   q'_j = (sum_i q_i * exp(trans[j,i])) * exp(em[t,j]) / q_0(prev)
// exp(trans) registers and the per-step barrier are SHARED by both chains;
// the two dot products interleave so each chain's latency hides under the
// other's issue. Chains run to max(lenA,lenB) with per-step freeze selects.
// Emissions: 3-stage pipeline (LDG group g+2 | exp of group g+1 | consume g).
// ---------------------------------------------------------------------------
__global__ void __launch_bounds__(32) crf_fused_kernel(
    const float* __restrict__ em,
    const int*   __restrict__ tags,
    const void*  __restrict__ mask,
    const float* __restrict__ trans,
    const float* __restrict__ startt,
    const float* __restrict__ endt,
    float*       __restrict__ out)
{
    const int bA = 2 * blockIdx.x;
    const int bB = bA + 1;
    const int l  = threadIdx.x;            // 0..31
    const int s0 = 2 * l, s1 = 2 * l + 1;
    const bool valid = (s0 < KK);          // l < 24
    const int e0 = valid ? s0 : (KK - 2);  // clamped pair base (8B aligned)

    __shared__ __align__(16) float shA[2][64];
    __shared__ __align__(16) float shB[2][64];

    // ---- sequence lengths (mask monotone prefix; dtype sniffed:
    //      mask[0,1] guaranteed true since lengths >= T/2) ----
    const unsigned char* mbp = (const unsigned char*)mask;
    const bool bytemask = (mbp[1] | mbp[2] | mbp[3]) != 0;
    int lenA = 0, lenB = 0;
    #pragma unroll
    for (int w = 0; w < 2; w++) {
        int b = w ? bB : bA;
        int cnt = 0;
        if (bytemask) {
            const unsigned char* m = mbp + b * TT;
            #pragma unroll
            for (int t = l; t < TT; t += 32) cnt += (m[t] != 0);
        } else {
            const unsigned int* m = (const unsigned int*)mask + b * TT;
            #pragma unroll
            for (int t = l; t < TT; t += 32) cnt += (m[t] != 0u);
        }
        #pragma unroll
        for (int o = 16; o; o >>= 1) cnt += __shfl_xor_sync(0xffffffffu, cnt, o);
        if (w) lenB = cnt; else lenA = cnt;
    }
    const int maxlen = (lenA > lenB) ? lenA : lenB;

    const size_t emA = (size_t)bA * TT * KK;
    const size_t emB = (size_t)bB * TT * KK;

    // ---- numerator scores ----
    float accA = 0.0f, accB = 0.0f;
    #pragma unroll
    for (int w = 0; w < 2; w++) {
        int b = w ? bB : bA;
        int len = w ? lenB : lenA;
        size_t eb = w ? emB : emA;
        const int base = b * TT;
        float acc = 0.0f;
        for (int k = 0; k * 32 < len; k++) {
            int t = k * 32 + l;
            if (t >= 1 && t < len) {
                int cur  = tags[base + t];
                int prev = tags[base + t - 1];
                acc += em[eb + (size_t)t * KK + cur] + trans[prev * KK + cur];
            }
        }
        #pragma unroll
        for (int o = 16; o; o >>= 1) acc += __shfl_xor_sync(0xffffffffu, acc, o);
        if (w) accB = acc; else accA = acc;
    }

    // ---- exp(transitions) rows (SHARED by both batches), packed f32x2 ----
    ull eTa[24], eTb[24];
    #pragma unroll
    for (int i = 0; i < 24; i++) {
        eTa[i] = valid ? pack2(__expf(trans[s0 * KK + 2 * i]),
                               __expf(trans[s0 * KK + 2 * i + 1])) : 0ULL;
        eTb[i] = valid ? pack2(__expf(trans[s1 * KK + 2 * i]),
                               __expf(trans[s1 * KK + 2 * i + 1])) : 0ULL;
    }
    const float eend0 = valid ? __expf(endt[s0]) : 0.0f;
    const float eend1 = valid ? __expf(endt[s1]) : 0.0f;

    // ---- init t = 0 for both batches ----
    float q0A, q1A, CA, rA = 1.0f, xcA = 1.0f;
    float q0B, q1B, CB, rB = 1.0f, xcB = 1.0f;
    {
        float a0 = valid ? (startt[s0] + em[emA + s0]) : 0.0f;
        float a1 = valid ? (startt[s1] + em[emA + s1]) : 0.0f;
        float c0 = __shfl_sync(0xffffffffu, a0, 0);
        q0A = valid ? __expf(a0 - c0) : 0.0f;
        q1A = valid ? __expf(a1 - c0) : 0.0f;
        CA = c0;
        ((float2*)shA[0])[l] = make_float2(q0A, q1A);
    }
    {
        float a0 = valid ? (startt[s0] + em[emB + s0]) : 0.0f;
        float a1 = valid ? (startt[s1] + em[emB + s1]) : 0.0f;
        float c0 = __shfl_sync(0xffffffffu, a0, 0);
        q0B = valid ? __expf(a0 - c0) : 0.0f;
        q1B = valid ? __expf(a1 - c0) : 0.0f;
        CB = c0;
        ((float2*)shB[0])[l] = make_float2(q0B, q1B);
    }
    __syncthreads();

    // ---- emission pipeline: prime (groups of 4, distance 8) ----
    float2 EAa[4], EBa[4], Ra[4];
    float2 EAb[4], EBb[4], Rb[4];
    #pragma unroll
    for (int s = 0; s < 4; s++) {           // exp for t = 1..4 (exposed once)
        int tt = 1 + s;
        float2 va = *(const float2*)&em[emA + (size_t)tt * KK + e0];
        float2 vb = *(const float2*)&em[emB + (size_t)tt * KK + e0];
        EAa[s] = make_float2(__expf(va.x), __expf(va.y));
        EAb[s] = make_float2(__expf(vb.x), __expf(vb.y));
    }
    #pragma unroll
    for (int s = 0; s < 4; s++) {           // raw for t = 5..8
        int tt = 5 + s;
        Ra[s] = *(const float2*)&em[emA + (size_t)tt * KK + e0];
        Rb[s] = *(const float2*)&em[emB + (size_t)tt * KK + e0];
    }

#define STEP2(RD, WR, EEA, EEB, TCUR) do {                                     \
    const double2* PA = (const double2*)shA[RD];                               \
    const double2* PB = (const double2*)shB[RD];                               \
    ull A0=0,A1=0,A2=0,A3=0,B0=0,B1=0,B2=0,B3=0;                               \
    ull G0=0,G1=0,G2=0,G3=0,H0=0,H1=0,H2=0,H3=0;                               \
    _Pragma("unroll")                                                          \
    for (int i = 0; i < 12; i += 2) {                                          \
        double2 pa0 = PA[i], pa1 = PA[i + 1];                                  \
        double2 pb0 = PB[i], pb1 = PB[i + 1];                                  \
        ull xa=__double_as_longlong(pa0.x), xb=__double_as_longlong(pa0.y);    \
        ull xc=__double_as_longlong(pa1.x), xd=__double_as_longlong(pa1.y);    \
        ull ya=__double_as_longlong(pb0.x), yb=__double_as_longlong(pb0.y);    \
        ull yc=__double_as_longlong(pb1.x), yd=__double_as_longlong(pb1.y);    \
        FFMA2(A0, xa, eTa[2*i+0], A0);  FFMA2(A1, xb, eTa[2*i+1], A1);         \
        FFMA2(A2, xc, eTa[2*i+2], A2);  FFMA2(A3, xd, eTa[2*i+3], A3);         \
        FFMA2(B0, xa, eTb[2*i+0], B0);  FFMA2(B1, xb, eTb[2*i+1], B1);         \
        FFMA2(B2, xc, eTb[2*i+2], B2);  FFMA2(B3, xd, eTb[2*i+3], B3);         \
        FFMA2(G0, ya, eTa[2*i+0], G0);  FFMA2(G1, yb, eTa[2*i+1], G1);         \
        FFMA2(G2, yc, eTa[2*i+2], G2);  FFMA2(G3, yd, eTa[2*i+3], G3);         \
        FFMA2(H0, ya, eTb[2*i+0], H0);  FFMA2(H1, yb, eTb[2*i+1], H1);         \
        FFMA2(H2, yc, eTb[2*i+2], H2);  FFMA2(H3, yd, eTb[2*i+3], H3);         \
    }                                                                          \
    FADD2(A0, A0, A1); FADD2(A2, A2, A3); FADD2(A0, A0, A2);                   \
    FADD2(B0, B0, B1); FADD2(B2, B2, B3); FADD2(B0, B0, B2);                   \
    FADD2(G0, G0, G1); FADD2(G2, G2, G3); FADD2(G0, G0, G2);                   \
    FADD2(H0, H0, H1); FADD2(H2, H2, H3); FADD2(H0, H0, H2);                   \
    float uA0 = ulo(A0) + uhi(A0);                                             \
    float uA1 = ulo(B0) + uhi(B0);                                             \
    float uB0 = ulo(G0) + uhi(G0);                                             \
    float uB1 = ulo(H0) + uhi(H0);                                             \
    const bool actA = (TCUR) < lenA;                                           \
    const bool actB = (TCUR) < lenB;                                           \
    CA += actA ? __logf(xcA) : 0.0f;                                           \
    CB += actB ? __logf(xcB) : 0.0f;                                           \
    q0A = actA ? uA0 * (EEA).x * rA : q0A;                                     \
    q1A = actA ? uA1 * (EEA).y * rA : q1A;                                     \
    q0B = actB ? uB0 * (EEB).x * rB : q0B;                                     \
    q1B = actB ? uB1 * (EEB).y * rB : q1B;                                     \
    ((float2*)shA[WR])[l] = make_float2(q0A, q1A);                             \
    ((float2*)shB[WR])[l] = make_float2(q0B, q1B);                             \
    xcA = __shfl_sync(0xffffffffu, q0A, 0);                                    \
    xcB = __shfl_sync(0xffffffffu, q0B, 0);                                    \
    __syncthreads();                   /* one nw=1 barrier for BOTH chains */  \
    rA = __fdividef(1.0f, xcA);                                                \
    rB = __fdividef(1.0f, xcB);                                                \
} while (0)

    // group of 4 steps: ENXT = exp(R) (loads issued last group, landed);
    // R refilled for group after next; 4 branch-free steps consume ECUR.
#define GROUP(ECa, ENa, ECb, ENb) do {                                        \
    _Pragma("unroll")                                                         \
    for (int s = 0; s < 4; s++) {                                             \
        ENa[s] = make_float2(__expf(Ra[s].x), __expf(Ra[s].y));               \
        ENb[s] = make_float2(__expf(Rb[s].x), __expf(Rb[s].y));               \
    }                                                                         \
    _Pragma("unroll")                                                         \
    for (int s = 0; s < 4; s++) {                                             \
        int tt = t0 + 8 + s; tt = (tt < TT) ? tt : (TT - 1);                  \
        Ra[s] = *(const float2*)&em[emA + (size_t)tt * KK + e0];              \
        Rb[s] = *(const float2*)&em[emB + (size_t)tt * KK + e0];              \
    }                                                                         \
    STEP2(0, 1, ECa[0], ECb[0], t0 + 0);                                      \
    STEP2(1, 0, ECa[1], ECb[1], t0 + 1);                                      \
    STEP2(0, 1, ECa[2], ECb[2], t0 + 2);                                      \
    STEP2(1, 0, ECa[3], ECb[3], t0 + 3);                                      \
    t0 += 4;                                                                  \
} while (0)

    int t0 = 1;
    int useA = 1;
    while (t0 + 4 <= maxlen) {
        if (useA) GROUP(EAa, EBa, EAb, EBb);
        else      GROUP(EBa, EAa, EBb, EAb);
        useA ^= 1;
    }
    // tail: 0..3 steps, same parity convention (t0 stays odd)
    {
        const int nrem = maxlen - t0;
        #pragma unroll
        for (int s = 0; s < 4; s++) {
            if (s >= nrem) break;
            float2 Ea = useA ? EAa[s] : EBa[s];
            float2 Eb = useA ? EAb[s] : EBb[s];
            if (s & 1) STEP2(1, 0, Ea, Eb, t0 + s);
            else       STEP2(0, 1, Ea, Eb, t0 + s);
        }
    }
#undef GROUP
#undef STEP2

    // ---- out[b] = score - (C + log( sum_j q_j * exp(end_j) )) ----
    float totA = q0A * eend0 + q1A * eend1;
    float totB = q0B * eend0 + q1B * eend1;
    #pragma unroll
    for (int o = 16; o; o >>= 1) {
        totA += __shfl_xor_sync(0xffffffffu, totA, o);
        totB += __shfl_xor_sync(0xffffffffu, totB, o);
    }

    if (l == 0) {
        int baseA = bA * TT;
        int tag0A = tags[baseA];
        float scoreA = startt[tag0A] + em[emA + tag0A] + accA
                     + endt[tags[baseA + lenA - 1]];
        out[bA] = scoreA - (CA + __logf(totA));

        int baseB = bB * TT;
        int tag0B = tags[baseB];
        float scoreB = startt[tag0B] + em[emB + tag0B] + accB
                     + endt[tags[baseB + lenB - 1]];
        out[bB] = scoreB - (CB + __logf(totB));
    }
}

extern "C" void kernel_launch(void* const* d_in, const int* in_sizes, int n_in,
                              void* d_out, int out_size)
{
    const float* em    = (const float*)d_in[0];
    const int*   tags  = (const int*)d_in[1];
    const void*  mask  = d_in[2];
    const float* trans = (const float*)d_in[3];
    const float* stt   = (const float*)d_in[4];
    const float* ent   = (const float*)d_in[5];
    float*       out   = (float*)d_out;

    crf_fused_kernel<<<BB / 2, 32>>>(em, tags, mask, trans, stt, ent, out);
}

// round 8
// speedup vs baseline: 2.1706x; 2.1706x over previous
#include <cuda_runtime.h>
#include <math_constants.h>

#define BB 512
#define TT 1024
#define KK 48

typedef unsigned long long ull;

__device__ __forceinline__ ull pack2(float lo, float hi) {
    return ((ull)__float_as_uint(hi) << 32) | (ull)__float_as_uint(lo);
}
__device__ __forceinline__ float ulo(ull v){ return __uint_as_float((unsigned)v); }
__device__ __forceinline__ float uhi(ull v){ return __uint_as_float((unsigned)(v >> 32)); }

#define FFMA2(d,a,b,c) asm("fma.rn.f32x2 %0, %1, %2, %3;" : "=l"(d) : "l"(a), "l"(b), "l"(c))
#define FADD2(d,a,b)   asm("add.rn.f32x2 %0, %1, %2;"     : "=l"(d) : "l"(a), "l"(b))

// ---------------------------------------------------------------------------
// One block (32 threads, 1 warp) per batch. Lane l owns states 2l and 2l+1
// (lanes 24..31: zero rows). Forward recurrence in LINEAR space:
//   q'_j = (sum_i q_i * exp(trans[j,i])) * exp(em[t,j]) / q_0(prev)
// with the uniform rescale one step stale (cancels algebraically) and the
// log-scale C on a scalar side chain. Emissions: 3-stage pipeline
// (LDG group g+2 | exp of group g+1 | consume g). Single-warp block =>
// __syncwarp() replaces __syncthreads (no BAR STS-drain on the chain);
// tail shortened via off-chain Er = E*r precompute.
// ---------------------------------------------------------------------------
__global__ void __launch_bounds__(32) crf_fused_kernel(
    const float* __restrict__ em,
    const int*   __restrict__ tags,
    const void*  __restrict__ mask,
    const float* __restrict__ trans,
    const float* __restrict__ startt,
    const float* __restrict__ endt,
    float*       __restrict__ out)
{
    const int b  = blockIdx.x;
    const int l  = threadIdx.x;            // 0..31
    const int s0 = 2 * l, s1 = 2 * l + 1;
    const bool valid = (s0 < KK);          // l < 24
    const int e0 = valid ? s0 : (KK - 2);  // clamped pair base (8B aligned)

    __shared__ __align__(16) float sh[2][64];

    // ---- sequence length (mask monotone prefix; dtype sniffed:
    //      mask[0,1] guaranteed true since lengths >= T/2) ----
    const unsigned char* mb = (const unsigned char*)mask;
    int cnt = 0;
    if (mb[1] | mb[2] | mb[3]) {
        const unsigned char* m = mb + b * TT;
        #pragma unroll
        for (int t = l; t < TT; t += 32) cnt += (m[t] != 0);
    } else {
        const unsigned int* m = (const unsigned int*)mask + b * TT;
        #pragma unroll
        for (int t = l; t < TT; t += 32) cnt += (m[t] != 0u);
    }
    #pragma unroll
    for (int o = 16; o; o >>= 1) cnt += __shfl_xor_sync(0xffffffffu, cnt, o);
    const int len = cnt;

    const size_t em_base = (size_t)b * TT * KK;

    // ---- numerator score ----
    float acc = 0.0f;
    {
        const int base = b * TT;
        for (int k = 0; k * 32 < len; k++) {
            int t = k * 32 + l;
            if (t >= 1 && t < len) {
                int cur  = tags[base + t];
                int prev = tags[base + t - 1];
                acc += em[em_base + (size_t)t * KK + cur] + trans[prev * KK + cur];
            }
        }
        #pragma unroll
        for (int o = 16; o; o >>= 1) acc += __shfl_xor_sync(0xffffffffu, acc, o);
    }

    // ---- exp(transitions) rows for both owned states (packed f32x2) ----
    ull eTa[24], eTb[24];
    #pragma unroll
    for (int i = 0; i < 24; i++) {
        eTa[i] = valid ? pack2(__expf(trans[s0 * KK + 2 * i]),
                               __expf(trans[s0 * KK + 2 * i + 1])) : 0ULL;
        eTb[i] = valid ? pack2(__expf(trans[s1 * KK + 2 * i]),
                               __expf(trans[s1 * KK + 2 * i + 1])) : 0ULL;
    }
    float eend0 = valid ? __expf(endt[s0]) : 0.0f;
    float eend1 = valid ? __expf(endt[s1]) : 0.0f;

    // ---- init t = 0 ----
    float a0 = valid ? (startt[s0] + em[em_base + s0]) : 0.0f;
    float a1 = valid ? (startt[s1] + em[em_base + s1]) : 0.0f;
    float c0 = __shfl_sync(0xffffffffu, a0, 0);
    float q0v = valid ? __expf(a0 - c0) : 0.0f;   // lane0.x == 1 exactly
    float q1v = valid ? __expf(a1 - c0) : 0.0f;
    ((float2*)sh[0])[l] = make_float2(q0v, q1v);
    float C = c0, r = 1.0f, xcur = 1.0f;
    __syncwarp();

    // ---- emission pipeline: prime ----
    float2 EA[8], EB[8], R[8];
    #pragma unroll
    for (int s = 0; s < 8; s++) {               // exp for t = 1..8 (exposed once)
        int tt = 1 + s; tt = (tt < TT) ? tt : (TT - 1);
        float2 v = *(const float2*)&em[em_base + (size_t)tt * KK + e0];
        EA[s] = make_float2(__expf(v.x), __expf(v.y));
    }
    #pragma unroll
    for (int s = 0; s < 8; s++) {               // raw for t = 9..16
        int tt = 9 + s; tt = (tt < TT) ? tt : (TT - 1);
        R[s] = *(const float2*)&em[em_base + (size_t)tt * KK + e0];
    }

#define STEP(RD, WR, EE) do {                                                  \
    float Er0 = (EE).x * r;           /* off-chain: r ready since last sync */ \
    float Er1 = (EE).y * r;                                                    \
    const double2* P2 = (const double2*)sh[RD];                                \
    ull A0=0,A1=0,A2=0,A3=0,B0=0,B1=0,B2=0,B3=0;                               \
    _Pragma("unroll")                                                          \
    for (int i = 0; i < 12; i += 2) {                                          \
        double2 qA = P2[i]; double2 qB = P2[i + 1];                            \
        ull xa=__double_as_longlong(qA.x), xb=__double_as_longlong(qA.y);      \
        ull xc=__double_as_longlong(qB.x), xd=__double_as_longlong(qB.y);      \
        FFMA2(A0, xa, eTa[2*i+0], A0);  FFMA2(A1, xb, eTa[2*i+1], A1);         \
        FFMA2(A2, xc, eTa[2*i+2], A2);  FFMA2(A3, xd, eTa[2*i+3], A3);         \
        FFMA2(B0, xa, eTb[2*i+0], B0);  FFMA2(B1, xb, eTb[2*i+1], B1);         \
        FFMA2(B2, xc, eTb[2*i+2], B2);  FFMA2(B3, xd, eTb[2*i+3], B3);         \
    }                                                                          \
    FADD2(A0, A0, A1); FADD2(A2, A2, A3); FADD2(A0, A0, A2);                   \
    FADD2(B0, B0, B1); FADD2(B2, B2, B3); FADD2(B0, B0, B2);                   \
    float u0 = ulo(A0) + uhi(A0);                                              \
    float u1 = ulo(B0) + uhi(B0);                                              \
    C += __logf(xcur);                /* scalar side chain */                  \
    q0v = u0 * Er0;                   /* single FMUL tail */                   \
    q1v = u1 * Er1;                                                            \
    ((float2*)sh[WR])[l] = make_float2(q0v, q1v);                              \
    xcur = __shfl_sync(0xffffffffu, q0v, 0);                                   \
    __syncwarp();                     /* single-warp ordering, no BAR drain */ \
    r = __fdividef(1.0f, xcur);       /* stale rescale, off-chain */           \
} while (0)

    // group: ECUR consumed now; ENXT = exp(R) (loads from last group, landed);
    // R refilled for the group after next. t0 stays odd -> RD = s&1.
#define GROUP(ECUR, ENXT) do {                                                 \
    _Pragma("unroll")                                                          \
    for (int s = 0; s < 8; s++)                                                \
        ENXT[s] = make_float2(__expf(R[s].x), __expf(R[s].y));                 \
    _Pragma("unroll")                                                          \
    for (int s = 0; s < 8; s++) {                                              \
        int tt = t0 + 16 + s; tt = (tt < TT) ? tt : (TT - 1);                  \
        R[s] = *(const float2*)&em[em_base + (size_t)tt * KK + e0];            \
    }                                                                          \
    {                                                                          \
        const int tend = (t0 + 8 < len) ? (t0 + 8) : len;                      \
        _Pragma("unroll")                                                      \
        for (int s = 0; s < 8; s++) {                                          \
            if (t0 + s >= tend) break;                                         \
            if (s & 1) STEP(1, 0, ECUR[s]);                                    \
            else       STEP(0, 1, ECUR[s]);                                    \
        }                                                                      \
    }                                                                          \
    t0 += 8;                                                                   \
} while (0)

    int t0 = 1;
    while (t0 < len) {
        GROUP(EA, EB);
        if (t0 >= len) break;
        GROUP(EB, EA);
    }
#undef GROUP
#undef STEP

    // ---- out = score - (C + log( sum_j q_j * exp(end_j) )) ----
    float tot = q0v * eend0 + q1v * eend1;
    #pragma unroll
    for (int o = 16; o; o >>= 1) tot += __shfl_xor_sync(0xffffffffu, tot, o);

    if (l == 0) {
        const int base = b * TT;
        int tag0 = tags[base];
        float score = startt[tag0] + em[em_base + tag0] + acc
                    + endt[tags[base + len - 1]];
        out[b] = score - (C + __logf(tot));
    }
}

extern "C" void kernel_launch(void* const* d_in, const int* in_sizes, int n_in,
                              void* d_out, int out_size)
{
    const float* em    = (const float*)d_in[0];
    const int*   tags  = (const int*)d_in[1];
    const void*  mask  = d_in[2];
    const float* trans = (const float*)d_in[3];
    const float* stt   = (const float*)d_in[4];
    const float* ent   = (const float*)d_in[5];
    float*       out   = (float*)d_out;

    crf_fused_kernel<<<BB, 32>>>(em, tags, mask, trans, stt, ent, out);
}